// round 15
// baseline (speedup 1.0000x reference)
#include <cuda_runtime.h>
#include <cuda_fp16.h>
#include <math.h>

#define B_ 4
#define S_ 2048
#define DM 1024
#define NH 16
#define DK 64
#define OUT_ELEMS ((size_t)B_ * S_ * DM)

// Scratch (no cudaMalloc allowed)
__device__ __half g_Q[(size_t)B_ * NH * S_ * DK];
__device__ __half g_K[(size_t)B_ * NH * S_ * DK];
__device__ __half g_V[(size_t)B_ * NH * S_ * DK];
__device__ float  g_ctxf[(size_t)B_ * S_ * DM];          // tf32-rounded f32
__device__ float  g_Wr[4 * (size_t)DM * DM];             // rounded weights

__device__ __forceinline__ unsigned f2tf(float x) {
    unsigned u;
    asm("cvt.rna.tf32.f32 %0, %1;" : "=r"(u) : "f"(x));
    return u;
}

__device__ __forceinline__ unsigned packh2(float a, float b) {
    __half2 h = __floats2half2_rn(a, b);
    return *reinterpret_cast<unsigned*>(&h);
}

__device__ __forceinline__ void mma8(float* c, const unsigned* a, const unsigned* b) {
    asm volatile(
        "mma.sync.aligned.m16n8k8.row.col.f32.tf32.tf32.f32 "
        "{%0,%1,%2,%3}, {%4,%5,%6,%7}, {%8,%9}, {%0,%1,%2,%3};"
        : "+f"(c[0]), "+f"(c[1]), "+f"(c[2]), "+f"(c[3])
        : "r"(a[0]), "r"(a[1]), "r"(a[2]), "r"(a[3]), "r"(b[0]), "r"(b[1]));
}

__device__ __forceinline__ void mma16(float* c, const unsigned* a, const unsigned* b) {
    asm volatile(
        "mma.sync.aligned.m16n8k16.row.col.f32.f16.f16.f32 "
        "{%0,%1,%2,%3}, {%4,%5,%6,%7}, {%8,%9}, {%0,%1,%2,%3};"
        : "+f"(c[0]), "+f"(c[1]), "+f"(c[2]), "+f"(c[3])
        : "r"(a[0]), "r"(a[1]), "r"(a[2]), "r"(a[3]), "r"(b[0]), "r"(b[1]));
}

__device__ __forceinline__ void ldsm2t(unsigned& r0, unsigned& r1, unsigned addr) {
    asm volatile("ldmatrix.sync.aligned.m8n8.x2.trans.shared.b16 {%0,%1}, [%2];"
                 : "=r"(r0), "=r"(r1) : "r"(addr));
}

__device__ __forceinline__ void cpasync16(unsigned saddr, const void* g) {
    asm volatile("cp.async.ca.shared.global [%0], [%1], 16;" :: "r"(saddr), "l"(g));
}
__device__ __forceinline__ void cp_commit() {
    asm volatile("cp.async.commit_group;");
}
// Wait so that tile t's group is complete, given last issued tile is min(t+2,15)
__device__ __forceinline__ void cp_wait_tile(int t, int last) {
    int rem = last - t;
    if (rem >= 2)      asm volatile("cp.async.wait_group 2;");
    else if (rem == 1) asm volatile("cp.async.wait_group 1;");
    else               asm volatile("cp.async.wait_group 0;");
}

// ---------------------------------------------------------------------------
// Weight pre-round, all four weights in ONE launch. grid = (256, 4).
// ---------------------------------------------------------------------------
__global__ void __launch_bounds__(256)
round_w4(const float* __restrict__ w0, const float* __restrict__ w1,
         const float* __restrict__ w2, const float* __restrict__ w3,
         float* __restrict__ dst)
{
    const float* src = (blockIdx.y == 0) ? w0 : (blockIdx.y == 1) ? w1
                     : (blockIdx.y == 2) ? w2 : w3;
    float* d = dst + (size_t)blockIdx.y * DM * DM;
    const int n4 = (DM * DM) / 4;
    for (int i = blockIdx.x * 256 + threadIdx.x; i < n4; i += gridDim.x * 256) {
        float4 v = reinterpret_cast<const float4*>(src)[i];
        uint4 u;
        u.x = f2tf(v.x); u.y = f2tf(v.y); u.z = f2tf(v.z); u.w = f2tf(v.w);
        reinterpret_cast<uint4*>(d)[i] = u;
    }
}

// ---------------------------------------------------------------------------
// Projection GEMM (R14 proven): 256 threads, 128x128x32, warp 64x32,
// cp.async dbl-buffer, 2 CTAs/SM, A rounded in-register, W pre-rounded.
// EPI 0 = head-split half store; EPI 1 = float [M,DM] store.
// ---------------------------------------------------------------------------
#define PSA 36
#define PSB 136
#define PROJ_A_WORDS (128 * PSA)
#define PROJ_B_WORDS (32 * PSB)
#define PROJ_SMEM ((2 * PROJ_A_WORDS + 2 * PROJ_B_WORDS) * 4)   // 71,680 B

template<int EPI>
__global__ void __launch_bounds__(256, 2)
gemm_proj(const float* __restrict__ A, const float* __restrict__ W,
          void* __restrict__ Cv, const float* __restrict__ bias)
{
    extern __shared__ float psm[];
    const unsigned sb = (unsigned)__cvta_generic_to_shared(psm);

    const int tid = threadIdx.x;
    const int lane = tid & 31, wid = tid >> 5;
    const int wm = (wid & 1) * 64, wn = (wid >> 1) * 32;
    const int bm = blockIdx.y * 128, bn = blockIdx.x * 128;

    auto issue = [&](int it) {
        const int k0 = it * 32, s = it & 1;
        #pragma unroll
        for (int i = 0; i < 4; ++i) {
            int f = tid + i * 256;
            int r = f >> 3, c4 = (f & 7) * 4;
            cpasync16(sb + (unsigned)(s * PROJ_A_WORDS + r * PSA + c4) * 4,
                      A + (size_t)(bm + r) * DM + k0 + c4);
        }
        #pragma unroll
        for (int i = 0; i < 4; ++i) {
            int f = tid + i * 256;
            int r2 = f >> 5, c2 = (f & 31) * 4;
            cpasync16(sb + (unsigned)(2 * PROJ_A_WORDS + s * PROJ_B_WORDS + r2 * PSB + c2) * 4,
                      W + (size_t)(k0 + r2) * DM + bn + c2);
        }
    };

    float acc[4][4][4] = {};

    issue(0); cp_commit();
    for (int it = 0; it < 32; ++it) {
        __syncthreads();
        if (it + 1 < 32) { issue(it + 1); cp_commit(); }
        if (it + 1 < 32) asm volatile("cp.async.wait_group 1;");
        else             asm volatile("cp.async.wait_group 0;");
        __syncthreads();
        const float* As = psm + (it & 1) * PROJ_A_WORDS;
        const unsigned* Bs = (const unsigned*)(psm + 2 * PROJ_A_WORDS + (it & 1) * PROJ_B_WORDS);

        #pragma unroll
        for (int kk = 0; kk < 4; ++kk) {
            unsigned afr[4][4], bfr[4][2];
            #pragma unroll
            for (int mi = 0; mi < 4; ++mi) {
                int r = wm + mi * 16 + (lane >> 2);
                int c = kk * 8 + (lane & 3);
                afr[mi][0] = f2tf(As[r * PSA + c]);
                afr[mi][1] = f2tf(As[(r + 8) * PSA + c]);
                afr[mi][2] = f2tf(As[r * PSA + c + 4]);
                afr[mi][3] = f2tf(As[(r + 8) * PSA + c + 4]);
            }
            #pragma unroll
            for (int ni = 0; ni < 4; ++ni) {
                int n = wn + ni * 8 + (lane >> 2);
                int c = kk * 8 + (lane & 3);
                bfr[ni][0] = Bs[c * PSB + n];
                bfr[ni][1] = Bs[(c + 4) * PSB + n];
            }
            #pragma unroll
            for (int mi = 0; mi < 4; ++mi)
                #pragma unroll
                for (int ni = 0; ni < 4; ++ni)
                    mma8(acc[mi][ni], afr[mi], bfr[ni]);
        }
    }

    #pragma unroll
    for (int mi = 0; mi < 4; ++mi)
        #pragma unroll
        for (int ni = 0; ni < 4; ++ni)
            #pragma unroll
            for (int e = 0; e < 4; ++e) {
                int m = bm + wm + mi * 16 + (lane >> 2) + ((e >= 2) ? 8 : 0);
                int n = bn + wn + ni * 8 + (lane & 3) * 2 + (e & 1);
                float v = acc[mi][ni][e] + bias[n];
                if (EPI == 0) {
                    int b = m >> 11, s = m & (S_ - 1);
                    int h = n >> 6, d = n & (DK - 1);
                    ((__half*)Cv)[(((size_t)b * NH + h) * S_ + s) * DK + d] = __float2half_rn(v);
                } else {
                    ((float*)Cv)[(size_t)m * DM + n] = v;
                }
            }
}

// ---------------------------------------------------------------------------
// Fused attention (fp16): 512 threads, 128 q-rows/CTA, 4-deep cp.async
// pipeline (one top barrier per tile; issue-after-barrier into buf (t+3)&3).
// ---------------------------------------------------------------------------
#define FQW  36                              // words per 72-half K/V/Q row
#define PSW  68                              // words per Ps row
#define TB   (128 * 72 * 2)                  // 18,432 B per tile buffer
#define PS_BYTES (128 * PSW * 4)             // 34,816 B
#define OFF_Q    0
#define OFF_K    TB                          // 18,432  (4 bufs -> 92,160)
#define OFF_V    (TB * 5)                    // 92,160  (4 bufs -> 165,888)
#define OFF_PS   (TB * 9)                    // 165,888
#define OFF_SINV (OFF_PS + PS_BYTES)         // 200,704
#define FUSED_SMEM (OFF_SINV + 512)          // 201,216 B

#define NT (S_ / 128)                        // 16 tiles

__global__ void __launch_bounds__(512, 1)
fused_attn(const __half* __restrict__ Q, const __half* __restrict__ Km,
           const __half* __restrict__ V, float* __restrict__ attn,
           float* __restrict__ ctx)
{
    extern __shared__ unsigned char smem_raw[];
    const unsigned* Qs32 = (const unsigned*)(smem_raw + OFF_Q);
    unsigned* Ps32 = (unsigned*)(smem_raw + OFF_PS);
    float* sSinv = (float*)(smem_raw + OFF_SINV);    // [128]
    float* rowss = (float*)(smem_raw + OFF_PS);      // [128][4] scratch pre-pass2

    const unsigned sb = (unsigned)__cvta_generic_to_shared(smem_raw);
    const int tid = threadIdx.x;
    const int lane = tid & 31, wid = tid >> 5;
    const int wm = (wid & 3) * 32;          // warp q-rows
    const int wn = (wid >> 2) * 32;         // score cols
    const int wn2 = (wid >> 2) * 16;        // AV d cols
    const int q0 = blockIdx.x * 128;
    const int bh = blockIdx.y;
    const float scale = 0.125f;

    const __half* Qb = Q + (size_t)bh * S_ * DK;
    const __half* Kb = Km + (size_t)bh * S_ * DK;
    const __half* Vb = V + (size_t)bh * S_ * DK;
    float* attn_b = attn + (size_t)bh * S_ * S_;

    auto issueQ = [&]() {
        #pragma unroll
        for (int i = 0; i < 2; ++i) {
            int f = tid + i * 512;
            int r = f >> 3, c = f & 7;
            cpasync16(sb + OFF_Q + r * 144 + c * 16,
                      Qb + (size_t)(q0 + r) * DK + c * 8);
        }
    };
    auto issueK = [&](int t) {
        #pragma unroll
        for (int i = 0; i < 2; ++i) {
            int f = tid + i * 512;
            int r = f >> 3, c = f & 7;
            cpasync16(sb + OFF_K + (t & 3) * TB + r * 144 + c * 16,
                      Kb + (size_t)(t * 128 + r) * DK + c * 8);
        }
    };
    auto issueV = [&](int t) {
        #pragma unroll
        for (int i = 0; i < 2; ++i) {
            int f = tid + i * 512;
            int r = f >> 3, c = f & 7;
            cpasync16(sb + OFF_V + (t & 3) * TB + r * 144 + c * 16,
                      Vb + (size_t)(t * 128 + r) * DK + c * 8);
        }
    };

    // ---------------- Pass 1: Q hoist + row sums ----------------
    issueQ(); cp_commit();                    // group Q
    issueK(0); cp_commit();
    issueK(1); cp_commit();
    issueK(2); cp_commit();
    asm volatile("cp.async.wait_group 3;");   // Q done
    __syncthreads();

    unsigned qfr[4][2][4];
    #pragma unroll
    for (int kk = 0; kk < 4; ++kk)
        #pragma unroll
        for (int mi = 0; mi < 2; ++mi) {
            int base = (wm + mi * 16 + (lane >> 2)) * FQW + kk * 8 + (lane & 3);
            qfr[kk][mi][0] = Qs32[base];
            qfr[kk][mi][1] = Qs32[base + 8 * FQW];
            qfr[kk][mi][2] = Qs32[base + 4];
            qfr[kk][mi][3] = Qs32[base + 8 * FQW + 4];
        }

    float sreg[2][2] = {};
    for (int t = 0; t < NT; ++t) {
        cp_wait_tile(t, min(t + 2, NT - 1));
        __syncthreads();                       // all warps done with buf (t+3)&3's last reader
        if (t + 3 < NT) { issueK(t + 3); cp_commit(); }
        const unsigned* Kc = (const unsigned*)(smem_raw + OFF_K + (t & 3) * TB);

        float sacc[2][4][4] = {};
        #pragma unroll
        for (int kk = 0; kk < 4; ++kk) {
            unsigned bfr[4][2];
            #pragma unroll
            for (int ni = 0; ni < 4; ++ni) {
                int n = wn + ni * 8 + (lane >> 2);
                int bw = n * FQW + kk * 8 + (lane & 3);
                bfr[ni][0] = Kc[bw];
                bfr[ni][1] = Kc[bw + 4];
            }
            #pragma unroll
            for (int mi = 0; mi < 2; ++mi)
                #pragma unroll
                for (int ni = 0; ni < 4; ++ni)
                    mma16(sacc[mi][ni], qfr[kk][mi], bfr[ni]);
        }

        #pragma unroll
        for (int mi = 0; mi < 2; ++mi)
            #pragma unroll
            for (int ni = 0; ni < 4; ++ni) {
                sreg[mi][0] += __expf(sacc[mi][ni][0] * scale)
                             + __expf(sacc[mi][ni][1] * scale);
                sreg[mi][1] += __expf(sacc[mi][ni][2] * scale)
                             + __expf(sacc[mi][ni][3] * scale);
            }
    }

    // ---------------- Row-sum reduction -> Sinv ----------------
    #pragma unroll
    for (int mi = 0; mi < 2; ++mi)
        #pragma unroll
        for (int e = 0; e < 2; ++e) {
            #pragma unroll
            for (int off = 1; off <= 2; off <<= 1)
                sreg[mi][e] += __shfl_xor_sync(0xFFFFFFFFu, sreg[mi][e], off);
        }
    __syncthreads();
    if ((lane & 3) == 0) {
        int g = wid >> 2;
        #pragma unroll
        for (int mi = 0; mi < 2; ++mi)
            #pragma unroll
            for (int e = 0; e < 2; ++e) {
                int r = wm + mi * 16 + (lane >> 2) + e * 8;
                rowss[r * 4 + g] = sreg[mi][e];
            }
    }
    __syncthreads();
    if (tid < 128) {
        float S = rowss[tid * 4] + rowss[tid * 4 + 1] + rowss[tid * 4 + 2] + rowss[tid * 4 + 3];
        sSinv[tid] = 1.0f / S;
    }
    __syncthreads();

    float Sf[2][2];
    #pragma unroll
    for (int mi = 0; mi < 2; ++mi)
        #pragma unroll
        for (int e = 0; e < 2; ++e)
            Sf[mi][e] = sSinv[wm + mi * 16 + (lane >> 2) + e * 8];
    __syncthreads();   // rowss reads done before Ps writes in pass 2

    // ---------------- Pass 2: recompute, write attn, Ps, AV ----------------
    float acco[2][2][4] = {};
    const int b = bh >> 4, h = bh & (NH - 1);

    issueK(0); issueV(0); cp_commit();
    issueK(1); issueV(1); cp_commit();
    issueK(2); issueV(2); cp_commit();
    for (int t = 0; t < NT; ++t) {
        cp_wait_tile(t, min(t + 2, NT - 1));
        __syncthreads();
        if (t + 3 < NT) { issueK(t + 3); issueV(t + 3); cp_commit(); }
        const unsigned* Kc = (const unsigned*)(smem_raw + OFF_K + (t & 3) * TB);

        float sacc[2][4][4] = {};
        #pragma unroll
        for (int kk = 0; kk < 4; ++kk) {
            unsigned afr[2][4], bfr[4][2];
            #pragma unroll
            for (int mi = 0; mi < 2; ++mi) {
                int base = (wm + mi * 16 + (lane >> 2)) * FQW + kk * 8 + (lane & 3);
                afr[mi][0] = Qs32[base];
                afr[mi][1] = Qs32[base + 8 * FQW];
                afr[mi][2] = Qs32[base + 4];
                afr[mi][3] = Qs32[base + 8 * FQW + 4];
            }
            #pragma unroll
            for (int ni = 0; ni < 4; ++ni) {
                int n = wn + ni * 8 + (lane >> 2);
                int bw = n * FQW + kk * 8 + (lane & 3);
                bfr[ni][0] = Kc[bw];
                bfr[ni][1] = Kc[bw + 4];
            }
            #pragma unroll
            for (int mi = 0; mi < 2; ++mi)
                #pragma unroll
                for (int ni = 0; ni < 4; ++ni)
                    mma16(sacc[mi][ni], afr[mi], bfr[ni]);
        }

        // p = exp(s*scale)*Sinv (fp32); write attn; stage half into Ps
        #pragma unroll
        for (int mi = 0; mi < 2; ++mi) {
            #pragma unroll
            for (int ni = 0; ni < 4; ++ni) {
                int rl = wm + mi * 16 + (lane >> 2);
                int cl = wn + ni * 8 + 2 * (lane & 3);
                float p0 = __expf(sacc[mi][ni][0] * scale) * Sf[mi][0];
                float p1 = __expf(sacc[mi][ni][1] * scale) * Sf[mi][0];
                float p2 = __expf(sacc[mi][ni][2] * scale) * Sf[mi][1];
                float p3 = __expf(sacc[mi][ni][3] * scale) * Sf[mi][1];
                size_t gr = (size_t)(q0 + rl) * S_ + t * 128 + cl;
                *reinterpret_cast<float2*>(attn_b + gr) = make_float2(p0, p1);
                *reinterpret_cast<float2*>(attn_b + gr + 8 * S_) = make_float2(p2, p3);
                int pw = rl * PSW + (cl >> 1);
                Ps32[pw] = packh2(p0, p1);
                Ps32[pw + 8 * PSW] = packh2(p2, p3);
            }
        }
        __syncthreads();                      // Ps column-quarters exchanged

        // AV: acco[128x64] += P[128x128] @ V[128x64]
        #pragma unroll
        for (int kk = 0; kk < 8; ++kk) {
            unsigned afr[2][4], bfr[2][2];
            #pragma unroll
            for (int mi = 0; mi < 2; ++mi) {
                int base = (wm + mi * 16 + (lane >> 2)) * PSW + kk * 8 + (lane & 3);
                afr[mi][0] = Ps32[base];
                afr[mi][1] = Ps32[base + 8 * PSW];
                afr[mi][2] = Ps32[base + 4];
                afr[mi][3] = Ps32[base + 8 * PSW + 4];
            }
            #pragma unroll
            for (int ni = 0; ni < 2; ++ni) {
                unsigned va = sb + OFF_V + (t & 3) * TB
                            + ((kk * 16 + (lane & 15)) * 72 + wn2 + ni * 8) * 2;
                ldsm2t(bfr[ni][0], bfr[ni][1], va);
            }
            #pragma unroll
            for (int mi = 0; mi < 2; ++mi)
                #pragma unroll
                for (int ni = 0; ni < 2; ++ni)
                    mma16(acco[mi][ni], afr[mi], bfr[ni]);
        }
    }

    // ctx store: tf32-rounded f32 (O-proj in-register f2tf is then idempotent)
    #pragma unroll
    for (int mi = 0; mi < 2; ++mi)
        #pragma unroll
        for (int ni = 0; ni < 2; ++ni)
            #pragma unroll
            for (int e = 0; e < 4; ++e) {
                int row = q0 + wm + mi * 16 + (lane >> 2) + ((e >= 2) ? 8 : 0);
                int d = wn2 + ni * 8 + (lane & 3) * 2 + (e & 1);
                ctx[((size_t)b * S_ + row) * DM + h * DK + d] =
                    __uint_as_float(f2tf(acco[mi][ni][e]));
            }
}

// ---------------------------------------------------------------------------
extern "C" void kernel_launch(void* const* d_in, const int* in_sizes, int n_in,
                              void* d_out, int out_size)
{
    const float* query = (const float*)d_in[0];
    const float* key   = (const float*)d_in[1];
    const float* value = (const float*)d_in[2];
    const float* w_q = (const float*)d_in[3];
    const float* b_q = (const float*)d_in[4];
    const float* w_k = (const float*)d_in[5];
    const float* b_k = (const float*)d_in[6];
    const float* w_v = (const float*)d_in[7];
    const float* b_v = (const float*)d_in[8];
    const float* w_o = (const float*)d_in[9];
    const float* b_o = (const float*)d_in[10];

    float* out = (float*)d_out;
    float* attn = out + OUT_ELEMS;   // (output, attn) concatenated

    __half* Qp; cudaGetSymbolAddress((void**)&Qp, g_Q);
    __half* Kp; cudaGetSymbolAddress((void**)&Kp, g_K);
    __half* Vp; cudaGetSymbolAddress((void**)&Vp, g_V);
    float* Cp; cudaGetSymbolAddress((void**)&Cp, g_ctxf);
    float* Wr; cudaGetSymbolAddress((void**)&Wr, g_Wr);

    cudaFuncSetAttribute(fused_attn, cudaFuncAttributeMaxDynamicSharedMemorySize,
                         FUSED_SMEM);
    cudaFuncSetAttribute(gemm_proj<0>, cudaFuncAttributeMaxDynamicSharedMemorySize,
                         PROJ_SMEM);
    cudaFuncSetAttribute(gemm_proj<1>, cudaFuncAttributeMaxDynamicSharedMemorySize,
                         PROJ_SMEM);

    // Pre-round all four weights in one launch
    round_w4<<<dim3(256, 4), 256>>>(w_q, w_k, w_v, w_o, Wr);

    dim3 gproj(DM / 128, (B_ * S_) / 128, 1);   // (8, 64)
    gemm_proj<0><<<gproj, 256, PROJ_SMEM>>>(query, Wr, Qp, b_q);
    gemm_proj<0><<<gproj, 256, PROJ_SMEM>>>(key,   Wr + (size_t)DM * DM, Kp, b_k);
    gemm_proj<0><<<gproj, 256, PROJ_SMEM>>>(value, Wr + 2 * (size_t)DM * DM, Vp, b_v);

    fused_attn<<<dim3(S_ / 128, B_ * NH), 512, FUSED_SMEM>>>(Qp, Kp, Vp, attn, Cp);

    gemm_proj<1><<<gproj, 256, PROJ_SMEM>>>(Cp, Wr + 3 * (size_t)DM * DM, out, b_o);
}

// round 16
// speedup vs baseline: 1.2045x; 1.2045x over previous
#include <cuda_runtime.h>
#include <cuda_fp16.h>
#include <math.h>

#define B_ 4
#define S_ 2048
#define DM 1024
#define NH 16
#define DK 64
#define OUT_ELEMS ((size_t)B_ * S_ * DM)

// Scratch (no cudaMalloc allowed)
__device__ __half g_Q[(size_t)B_ * NH * S_ * DK];
__device__ __half g_K[(size_t)B_ * NH * S_ * DK];
__device__ __half g_V[(size_t)B_ * NH * S_ * DK];
__device__ __half g_ctx[(size_t)B_ * S_ * DM];
__device__ __half g_Wt[4 * (size_t)DM * DM];     // transposed fp16 weights [n][k]

__device__ __forceinline__ unsigned packh2(float a, float b) {
    __half2 h = __floats2half2_rn(a, b);
    return *reinterpret_cast<unsigned*>(&h);
}

__device__ __forceinline__ void mma16(float* c, const unsigned* a, const unsigned* b) {
    asm volatile(
        "mma.sync.aligned.m16n8k16.row.col.f32.f16.f16.f32 "
        "{%0,%1,%2,%3}, {%4,%5,%6,%7}, {%8,%9}, {%0,%1,%2,%3};"
        : "+f"(c[0]), "+f"(c[1]), "+f"(c[2]), "+f"(c[3])
        : "r"(a[0]), "r"(a[1]), "r"(a[2]), "r"(a[3]), "r"(b[0]), "r"(b[1]));
}

__device__ __forceinline__ void ldsm2t(unsigned& r0, unsigned& r1, unsigned addr) {
    asm volatile("ldmatrix.sync.aligned.m8n8.x2.trans.shared.b16 {%0,%1}, [%2];"
                 : "=r"(r0), "=r"(r1) : "r"(addr));
}

__device__ __forceinline__ void cpasync16(unsigned saddr, const void* g) {
    asm volatile("cp.async.ca.shared.global [%0], [%1], 16;" :: "r"(saddr), "l"(g));
}
__device__ __forceinline__ void cp_commit() {
    asm volatile("cp.async.commit_group;");
}
__device__ __forceinline__ void cp_wait(bool keep_one) {
    if (keep_one) asm volatile("cp.async.wait_group 1;");
    else          asm volatile("cp.async.wait_group 0;");
}

// ---------------------------------------------------------------------------
// Transpose + fp16-convert all four weights: Wt[n][k] = half(W[k][n]).
// grid (32, 32, 4), block 256 (32x8), smem-tiled.
// ---------------------------------------------------------------------------
__global__ void __launch_bounds__(256)
transpose_w4(const float* __restrict__ w0, const float* __restrict__ w1,
             const float* __restrict__ w2, const float* __restrict__ w3,
             __half* __restrict__ dst)
{
    __shared__ float tile[32][33];
    const float* src = (blockIdx.z == 0) ? w0 : (blockIdx.z == 1) ? w1
                     : (blockIdx.z == 2) ? w2 : w3;
    __half* d = dst + (size_t)blockIdx.z * DM * DM;
    const int k0 = blockIdx.y * 32, n0 = blockIdx.x * 32;
    const int tx = threadIdx.x & 31, ty = threadIdx.x >> 5;

    #pragma unroll
    for (int j = 0; j < 32; j += 8)
        tile[ty + j][tx] = src[(size_t)(k0 + ty + j) * DM + n0 + tx];
    __syncthreads();
    #pragma unroll
    for (int j = 0; j < 32; j += 8)
        d[(size_t)(n0 + ty + j) * DM + k0 + tx] = __float2half_rn(tile[tx][ty + j]);
}

// ---------------------------------------------------------------------------
// Projection GEMM (fp16 mma16): 256 threads, 128x128x32, warp 64x32,
// cp.async dbl-buffer, 2 CTAs/SM.
// B = Wt[n][k] half, stride 40 halfs (conflict-free b-frags).
// AH=0: A f32 (stride 40 f32, LDS.64 + packh2);  AH=1: A half (stride 40 h).
// EPI 0 = head-split half store; EPI 1 = plain float [M,DM] store.
// ---------------------------------------------------------------------------
#define PA_F32_BYTES (128 * 40 * 4)      // 20,480 per A f32 buffer
#define PA_H_BYTES   (128 * 40 * 2)      // 10,240 per A half buffer
#define PB_BYTES     (128 * 40 * 2)      // 10,240 per B buffer

template<int AH, int EPI>
__global__ void __launch_bounds__(256, 2)
gemm_proj(const void* __restrict__ Av, const __half* __restrict__ Wt,
          void* __restrict__ Cv, const float* __restrict__ bias)
{
    extern __shared__ unsigned char psm[];
    constexpr int AWB = AH ? PA_H_BYTES : PA_F32_BYTES;
    constexpr int OFFB = 2 * AWB;
    const unsigned sb = (unsigned)__cvta_generic_to_shared(psm);

    const int tid = threadIdx.x;
    const int lane = tid & 31, wid = tid >> 5;
    const int tig = lane >> 2, k2 = lane & 3;
    const int wm = (wid & 1) * 64, wn = (wid >> 1) * 32;
    const int bm = blockIdx.y * 128, bn = blockIdx.x * 128;

    auto issue = [&](int it) {
        const int k0 = it * 32, s = it & 1;
        if (AH == 0) {
            const float* A = (const float*)Av;
            #pragma unroll
            for (int i = 0; i < 4; ++i) {
                int f = tid + i * 256;
                int r = f >> 3, c4 = (f & 7) * 4;
                cpasync16(sb + s * AWB + (r * 40 + c4) * 4,
                          A + (size_t)(bm + r) * DM + k0 + c4);
            }
        } else {
            const __half* A = (const __half*)Av;
            #pragma unroll
            for (int i = 0; i < 2; ++i) {
                int f = tid + i * 256;
                int r = f >> 2, c8 = (f & 3) * 8;
                cpasync16(sb + s * AWB + (r * 40 + c8) * 2,
                          A + (size_t)(bm + r) * DM + k0 + c8);
            }
        }
        #pragma unroll
        for (int i = 0; i < 2; ++i) {
            int f = tid + i * 256;
            int r = f >> 2, c8 = (f & 3) * 8;
            cpasync16(sb + OFFB + s * PB_BYTES + (r * 40 + c8) * 2,
                      Wt + (size_t)(bn + r) * DM + k0 + c8);
        }
    };

    float acc[4][4][4] = {};

    issue(0); cp_commit();
    for (int it = 0; it < 32; ++it) {
        __syncthreads();
        if (it + 1 < 32) { issue(it + 1); cp_commit(); }
        cp_wait(it + 1 < 32);
        __syncthreads();
        const float* Asf = (const float*)(psm + (it & 1) * AWB);
        const unsigned* Ash2 = (const unsigned*)(psm + (it & 1) * AWB);
        const unsigned* Bs = (const unsigned*)(psm + OFFB + (it & 1) * PB_BYTES);

        #pragma unroll
        for (int kk = 0; kk < 2; ++kk) {
            unsigned afr[4][4], bfr[4][2];
            #pragma unroll
            for (int mi = 0; mi < 4; ++mi) {
                int r = wm + mi * 16 + tig;
                if (AH == 0) {
                    float2 v0 = *reinterpret_cast<const float2*>(&Asf[r * 40 + kk * 16 + 2 * k2]);
                    float2 v1 = *reinterpret_cast<const float2*>(&Asf[(r + 8) * 40 + kk * 16 + 2 * k2]);
                    float2 v2 = *reinterpret_cast<const float2*>(&Asf[r * 40 + kk * 16 + 2 * k2 + 8]);
                    float2 v3 = *reinterpret_cast<const float2*>(&Asf[(r + 8) * 40 + kk * 16 + 2 * k2 + 8]);
                    afr[mi][0] = packh2(v0.x, v0.y);
                    afr[mi][1] = packh2(v1.x, v1.y);
                    afr[mi][2] = packh2(v2.x, v2.y);
                    afr[mi][3] = packh2(v3.x, v3.y);
                } else {
                    int base = r * 20 + kk * 8 + k2;
                    afr[mi][0] = Ash2[base];
                    afr[mi][1] = Ash2[base + 8 * 20];
                    afr[mi][2] = Ash2[base + 4];
                    afr[mi][3] = Ash2[base + 8 * 20 + 4];
                }
            }
            #pragma unroll
            for (int ni = 0; ni < 4; ++ni) {
                int n = wn + ni * 8 + tig;
                int bw = n * 20 + kk * 8 + k2;
                bfr[ni][0] = Bs[bw];
                bfr[ni][1] = Bs[bw + 4];
            }
            #pragma unroll
            for (int mi = 0; mi < 4; ++mi)
                #pragma unroll
                for (int ni = 0; ni < 4; ++ni)
                    mma16(acc[mi][ni], afr[mi], bfr[ni]);
        }
    }

    #pragma unroll
    for (int mi = 0; mi < 4; ++mi)
        #pragma unroll
        for (int ni = 0; ni < 4; ++ni)
            #pragma unroll
            for (int e = 0; e < 4; ++e) {
                int m = bm + wm + mi * 16 + tig + ((e >= 2) ? 8 : 0);
                int n = bn + wn + ni * 8 + k2 * 2 + (e & 1);
                float v = acc[mi][ni][e] + bias[n];
                if (EPI == 0) {
                    int b = m >> 11, s = m & (S_ - 1);
                    int h = n >> 6, d = n & (DK - 1);
                    ((__half*)Cv)[(((size_t)b * NH + h) * S_ + s) * DK + d] = __float2half_rn(v);
                } else {
                    ((float*)Cv)[(size_t)m * DM + n] = v;
                }
            }
}

#define PROJ_SMEM0 (2 * PA_F32_BYTES + 2 * PB_BYTES)   // 61,440
#define PROJ_SMEM1 (2 * PA_H_BYTES + 2 * PB_BYTES)     // 40,960

// ---------------------------------------------------------------------------
// Fused attention (fp16, PROVEN R12 config): 512 threads, 128 q-rows/CTA.
// ---------------------------------------------------------------------------
#define FQW  36                              // words per 72-half K/V/Q row
#define PSW  68                              // words per Ps row
#define TB   (128 * 72 * 2)                  // 18,432 B per tile buffer
#define PS_BYTES (128 * PSW * 4)             // 34,816 B
#define OFF_Q    0
#define OFF_K    TB                          // 18,432 (2 bufs)
#define OFF_V    (TB * 3)                    // 55,296 (2 bufs)
#define OFF_PS   (TB * 5)                    // 92,160
#define OFF_SINV (OFF_PS + PS_BYTES)         // 126,976
#define FUSED_SMEM (OFF_SINV + 512)          // 127,488 B

__global__ void __launch_bounds__(512, 1)
fused_attn(const __half* __restrict__ Q, const __half* __restrict__ Km,
           const __half* __restrict__ V, float* __restrict__ attn,
           __half* __restrict__ ctx)
{
    extern __shared__ unsigned char smem_raw[];
    const unsigned* Qs32 = (const unsigned*)(smem_raw + OFF_Q);
    unsigned* Ps32 = (unsigned*)(smem_raw + OFF_PS);
    float* sSinv = (float*)(smem_raw + OFF_SINV);    // [128]
    float* rowss = (float*)(smem_raw + OFF_PS);      // [128][4] scratch pre-pass2

    const unsigned sb = (unsigned)__cvta_generic_to_shared(smem_raw);
    const int tid = threadIdx.x;
    const int lane = tid & 31, wid = tid >> 5;
    const int wm = (wid & 3) * 32;          // warp q-rows
    const int wn = (wid >> 2) * 32;         // score cols
    const int wn2 = (wid >> 2) * 16;        // AV d cols
    const int q0 = blockIdx.x * 128;
    const int bh = blockIdx.y;
    const float scale = 0.125f;

    const __half* Qb = Q + (size_t)bh * S_ * DK;
    const __half* Kb = Km + (size_t)bh * S_ * DK;
    const __half* Vb = V + (size_t)bh * S_ * DK;
    float* attn_b = attn + (size_t)bh * S_ * S_;

    auto issueQ = [&]() {
        #pragma unroll
        for (int i = 0; i < 2; ++i) {
            int f = tid + i * 512;
            int r = f >> 3, c = f & 7;
            cpasync16(sb + OFF_Q + r * 144 + c * 16,
                      Qb + (size_t)(q0 + r) * DK + c * 8);
        }
    };
    auto issueK = [&](int t) {
        #pragma unroll
        for (int i = 0; i < 2; ++i) {
            int f = tid + i * 512;
            int r = f >> 3, c = f & 7;
            cpasync16(sb + OFF_K + (t & 1) * TB + r * 144 + c * 16,
                      Kb + (size_t)(t * 128 + r) * DK + c * 8);
        }
    };
    auto issueV = [&](int t) {
        #pragma unroll
        for (int i = 0; i < 2; ++i) {
            int f = tid + i * 512;
            int r = f >> 3, c = f & 7;
            cpasync16(sb + OFF_V + (t & 1) * TB + r * 144 + c * 16,
                      Vb + (size_t)(t * 128 + r) * DK + c * 8);
        }
    };

    // ---------------- Pass 1: Q hoist + row sums ----------------
    issueQ(); cp_commit();        // G0
    issueK(0); cp_commit();       // G1
    asm volatile("cp.async.wait_group 1;");   // Q done
    __syncthreads();

    unsigned qfr[4][2][4];
    #pragma unroll
    for (int kk = 0; kk < 4; ++kk)
        #pragma unroll
        for (int mi = 0; mi < 2; ++mi) {
            int base = (wm + mi * 16 + (lane >> 2)) * FQW + kk * 8 + (lane & 3);
            qfr[kk][mi][0] = Qs32[base];
            qfr[kk][mi][1] = Qs32[base + 8 * FQW];
            qfr[kk][mi][2] = Qs32[base + 4];
            qfr[kk][mi][3] = Qs32[base + 8 * FQW + 4];
        }

    float sreg[2][2] = {};
    for (int t = 0; t < S_ / 128; ++t) {
        __syncthreads();
        if (t + 1 < S_ / 128) { issueK(t + 1); cp_commit(); }
        cp_wait(t + 1 < S_ / 128);
        __syncthreads();
        const unsigned* Kc = (const unsigned*)(smem_raw + OFF_K + (t & 1) * TB);

        float sacc[2][4][4] = {};
        #pragma unroll
        for (int kk = 0; kk < 4; ++kk) {
            unsigned bfr[4][2];
            #pragma unroll
            for (int ni = 0; ni < 4; ++ni) {
                int n = wn + ni * 8 + (lane >> 2);
                int bw = n * FQW + kk * 8 + (lane & 3);
                bfr[ni][0] = Kc[bw];
                bfr[ni][1] = Kc[bw + 4];
            }
            #pragma unroll
            for (int mi = 0; mi < 2; ++mi)
                #pragma unroll
                for (int ni = 0; ni < 4; ++ni)
                    mma16(sacc[mi][ni], qfr[kk][mi], bfr[ni]);
        }

        #pragma unroll
        for (int mi = 0; mi < 2; ++mi)
            #pragma unroll
            for (int ni = 0; ni < 4; ++ni) {
                sreg[mi][0] += __expf(sacc[mi][ni][0] * scale)
                             + __expf(sacc[mi][ni][1] * scale);
                sreg[mi][1] += __expf(sacc[mi][ni][2] * scale)
                             + __expf(sacc[mi][ni][3] * scale);
            }
    }

    // ---------------- Row-sum reduction -> Sinv ----------------
    #pragma unroll
    for (int mi = 0; mi < 2; ++mi)
        #pragma unroll
        for (int e = 0; e < 2; ++e) {
            #pragma unroll
            for (int off = 1; off <= 2; off <<= 1)
                sreg[mi][e] += __shfl_xor_sync(0xFFFFFFFFu, sreg[mi][e], off);
        }
    __syncthreads();
    if ((lane & 3) == 0) {
        int g = wid >> 2;
        #pragma unroll
        for (int mi = 0; mi < 2; ++mi)
            #pragma unroll
            for (int e = 0; e < 2; ++e) {
                int r = wm + mi * 16 + (lane >> 2) + e * 8;
                rowss[r * 4 + g] = sreg[mi][e];
            }
    }
    __syncthreads();
    if (tid < 128) {
        float S = rowss[tid * 4] + rowss[tid * 4 + 1] + rowss[tid * 4 + 2] + rowss[tid * 4 + 3];
        sSinv[tid] = 1.0f / S;
    }
    __syncthreads();

    float Sf[2][2];
    #pragma unroll
    for (int mi = 0; mi < 2; ++mi)
        #pragma unroll
        for (int e = 0; e < 2; ++e)
            Sf[mi][e] = sSinv[wm + mi * 16 + (lane >> 2) + e * 8];
    __syncthreads();   // rowss reads done before Ps writes in pass 2

    // ---------------- Pass 2: recompute, write attn, Ps, AV ----------------
    float acco[2][2][4] = {};
    const int b = bh >> 4, h = bh & (NH - 1);

    issueK(0); issueV(0); cp_commit();
    for (int t = 0; t < S_ / 128; ++t) {
        __syncthreads();
        if (t + 1 < S_ / 128) { issueK(t + 1); issueV(t + 1); cp_commit(); }
        cp_wait(t + 1 < S_ / 128);
        __syncthreads();
        const unsigned* Kc = (const unsigned*)(smem_raw + OFF_K + (t & 1) * TB);

        float sacc[2][4][4] = {};
        #pragma unroll
        for (int kk = 0; kk < 4; ++kk) {
            unsigned afr[2][4], bfr[4][2];
            #pragma unroll
            for (int mi = 0; mi < 2; ++mi) {
                int base = (wm + mi * 16 + (lane >> 2)) * FQW + kk * 8 + (lane & 3);
                afr[mi][0] = Qs32[base];
                afr[mi][1] = Qs32[base + 8 * FQW];
                afr[mi][2] = Qs32[base + 4];
                afr[mi][3] = Qs32[base + 8 * FQW + 4];
            }
            #pragma unroll
            for (int ni = 0; ni < 4; ++ni) {
                int n = wn + ni * 8 + (lane >> 2);
                int bw = n * FQW + kk * 8 + (lane & 3);
                bfr[ni][0] = Kc[bw];
                bfr[ni][1] = Kc[bw + 4];
            }
            #pragma unroll
            for (int mi = 0; mi < 2; ++mi)
                #pragma unroll
                for (int ni = 0; ni < 4; ++ni)
                    mma16(sacc[mi][ni], afr[mi], bfr[ni]);
        }

        // p = exp(s*scale)*Sinv (fp32); write attn; stage half into Ps
        #pragma unroll
        for (int mi = 0; mi < 2; ++mi) {
            #pragma unroll
            for (int ni = 0; ni < 4; ++ni) {
                int rl = wm + mi * 16 + (lane >> 2);
                int cl = wn + ni * 8 + 2 * (lane & 3);
                float p0 = __expf(sacc[mi][ni][0] * scale) * Sf[mi][0];
                float p1 = __expf(sacc[mi][ni][1] * scale) * Sf[mi][0];
                float p2 = __expf(sacc[mi][ni][2] * scale) * Sf[mi][1];
                float p3 = __expf(sacc[mi][ni][3] * scale) * Sf[mi][1];
                size_t gr = (size_t)(q0 + rl) * S_ + t * 128 + cl;
                *reinterpret_cast<float2*>(attn_b + gr) = make_float2(p0, p1);
                *reinterpret_cast<float2*>(attn_b + gr + 8 * S_) = make_float2(p2, p3);
                int pw = rl * PSW + (cl >> 1);
                Ps32[pw] = packh2(p0, p1);
                Ps32[pw + 8 * PSW] = packh2(p2, p3);
            }
        }
        __syncthreads();

        // AV: acco[128x64] += P[128x128] @ V[128x64]
        #pragma unroll
        for (int kk = 0; kk < 8; ++kk) {
            unsigned afr[2][4], bfr[2][2];
            #pragma unroll
            for (int mi = 0; mi < 2; ++mi) {
                int base = (wm + mi * 16 + (lane >> 2)) * PSW + kk * 8 + (lane & 3);
                afr[mi][0] = Ps32[base];
                afr[mi][1] = Ps32[base + 8 * PSW];
                afr[mi][2] = Ps32[base + 4];
                afr[mi][3] = Ps32[base + 8 * PSW + 4];
            }
            #pragma unroll
            for (int ni = 0; ni < 2; ++ni) {
                unsigned va = sb + OFF_V + (t & 1) * TB
                            + ((kk * 16 + (lane & 15)) * 72 + wn2 + ni * 8) * 2;
                ldsm2t(bfr[ni][0], bfr[ni][1], va);
            }
            #pragma unroll
            for (int mi = 0; mi < 2; ++mi)
                #pragma unroll
                for (int ni = 0; ni < 2; ++ni)
                    mma16(acco[mi][ni], afr[mi], bfr[ni]);
        }
    }

    // ctx half store (already normalized) — feeds half-A O-projection
    #pragma unroll
    for (int mi = 0; mi < 2; ++mi)
        #pragma unroll
        for (int ni = 0; ni < 2; ++ni)
            #pragma unroll
            for (int e = 0; e < 4; ++e) {
                int row = q0 + wm + mi * 16 + (lane >> 2) + ((e >= 2) ? 8 : 0);
                int d = wn2 + ni * 8 + (lane & 3) * 2 + (e & 1);
                ctx[((size_t)b * S_ + row) * DM + h * DK + d] =
                    __float2half_rn(acco[mi][ni][e]);
            }
}

// ---------------------------------------------------------------------------
extern "C" void kernel_launch(void* const* d_in, const int* in_sizes, int n_in,
                              void* d_out, int out_size)
{
    const float* query = (const float*)d_in[0];
    const float* key   = (const float*)d_in[1];
    const float* value = (const float*)d_in[2];
    const float* w_q = (const float*)d_in[3];
    const float* b_q = (const float*)d_in[4];
    const float* w_k = (const float*)d_in[5];
    const float* b_k = (const float*)d_in[6];
    const float* w_v = (const float*)d_in[7];
    const float* b_v = (const float*)d_in[8];
    const float* w_o = (const float*)d_in[9];
    const float* b_o = (const float*)d_in[10];

    float* out = (float*)d_out;
    float* attn = out + OUT_ELEMS;   // (output, attn) concatenated

    __half* Qp; cudaGetSymbolAddress((void**)&Qp, g_Q);
    __half* Kp; cudaGetSymbolAddress((void**)&Kp, g_K);
    __half* Vp; cudaGetSymbolAddress((void**)&Vp, g_V);
    __half* Cp; cudaGetSymbolAddress((void**)&Cp, g_ctx);
    __half* Wt; cudaGetSymbolAddress((void**)&Wt, g_Wt);

    cudaFuncSetAttribute(fused_attn, cudaFuncAttributeMaxDynamicSharedMemorySize,
                         FUSED_SMEM);
    cudaFuncSetAttribute((gemm_proj<0, 0>), cudaFuncAttributeMaxDynamicSharedMemorySize,
                         PROJ_SMEM0);
    cudaFuncSetAttribute((gemm_proj<1, 1>), cudaFuncAttributeMaxDynamicSharedMemorySize,
                         PROJ_SMEM1);

    // Transpose + convert all four weights to fp16 [n][k] in one launch
    transpose_w4<<<dim3(32, 32, 4), 256>>>(w_q, w_k, w_v, w_o, Wt);

    dim3 gproj(DM / 128, (B_ * S_) / 128, 1);   // (8, 64)
    gemm_proj<0, 0><<<gproj, 256, PROJ_SMEM0>>>(query, Wt, Qp, b_q);
    gemm_proj<0, 0><<<gproj, 256, PROJ_SMEM0>>>(key,   Wt + (size_t)DM * DM, Kp, b_k);
    gemm_proj<0, 0><<<gproj, 256, PROJ_SMEM0>>>(value, Wt + 2 * (size_t)DM * DM, Vp, b_v);

    fused_attn<<<dim3(S_ / 128, B_ * NH), 512, FUSED_SMEM>>>(Qp, Kp, Vp, attn, Cp);

    gemm_proj<1, 1><<<gproj, 256, PROJ_SMEM1>>>(Cp, Wt + 3 * (size_t)DM * DM, out, b_o);
}